// round 1
// baseline (speedup 1.0000x reference)
#include <cuda_runtime.h>
#include <math.h>

#define E 64
#define TOK_PER_BLK 128
#define MAX_TOK 16384
#define MAX_CHUNKS (MAX_TOK / TOK_PER_BLK)

// Scratch (no allocations allowed)
__device__ int   g_idx[MAX_TOK];
__device__ float g_gate[MAX_TOK];
__device__ int   g_hist[MAX_CHUNKS * E];
__device__ int   g_base[MAX_CHUNKS * E];

// ---------------------------------------------------------------------------
// Kernel 0: zero-fill output (dominant cost: ~671 MB of stores)
// ---------------------------------------------------------------------------
__global__ void zero_fill(float4* __restrict__ out4, size_t n4,
                          float* __restrict__ out, size_t n_total) {
    size_t i = blockIdx.x * (size_t)blockDim.x + threadIdx.x;
    size_t stride = gridDim.x * (size_t)blockDim.x;
    float4 z = make_float4(0.f, 0.f, 0.f, 0.f);
    for (; i < n4; i += stride) out4[i] = z;
    // scalar tail (if out_size % 4 != 0)
    if (blockIdx.x == 0 && threadIdx.x < (n_total - n4 * 4)) {
        out[n4 * 4 + threadIdx.x] = 0.f;
    }
}

// ---------------------------------------------------------------------------
// Kernel 1: per-token argmax + softmax prob at argmax + per-chunk histogram
// p(top1) = exp(x_top1 - m) / sum_i exp(x_i - m) = 1 / sum_i exp(x_i - x_max)
// ---------------------------------------------------------------------------
__global__ void route_kernel(const float* __restrict__ in, int s) {
    __shared__ float tile[TOK_PER_BLK][E + 1];  // +1 pad: conflict-free row reads
    __shared__ int hist[E];

    int blk  = blockIdx.x;
    int tid  = threadIdx.x;          // 128 threads
    int base = blk * TOK_PER_BLK;
    int tokens = s - base;
    if (tokens > TOK_PER_BLK) tokens = TOK_PER_BLK;

    // coalesced float4 load of [tokens x 64] into shared
    const float4* in4 = (const float4*)(in + (size_t)base * E);
    int n4 = tokens * E / 4;
    for (int i = tid; i < n4; i += blockDim.x) {
        float4 v = in4[i];
        int fl = i * 4;
        int t = fl >> 6;        // / 64
        int k = fl & 63;
        tile[t][k]     = v.x;
        tile[t][k + 1] = v.y;
        tile[t][k + 2] = v.z;
        tile[t][k + 3] = v.w;
    }
    if (tid < E) hist[tid] = 0;
    __syncthreads();

    if (tid < tokens) {
        // first-index argmax (matches jnp.argmax tie-breaking)
        float m = tile[tid][0];
        int am = 0;
#pragma unroll
        for (int k = 1; k < E; k++) {
            float v = tile[tid][k];
            if (v > m) { m = v; am = k; }
        }
        float sum = 0.f;
#pragma unroll
        for (int k = 0; k < E; k++)
            sum += __expf(tile[tid][k] - m);

        g_idx[base + tid]  = am;
        g_gate[base + tid] = 1.0f / sum;
        atomicAdd(&hist[am], 1);
    }
    __syncthreads();
    if (tid < E) g_hist[blk * E + tid] = hist[tid];
}

// ---------------------------------------------------------------------------
// Kernel 2: exclusive prefix over chunks, per expert (64 experts x nchunks)
// ---------------------------------------------------------------------------
__global__ void prefix_kernel(int nchunks) {
    int e = threadIdx.x;  // 64 threads
    int run = 0;
    for (int b = 0; b < nchunks; b++) {
        g_base[b * E + e] = run;
        run += g_hist[b * E + e];
    }
}

// ---------------------------------------------------------------------------
// Kernel 3: in-order per-chunk scan + sparse scatter of gate + mask
// ---------------------------------------------------------------------------
__global__ void scatter_kernel(float* __restrict__ out, int s, int cap,
                               size_t mask_off, int write_mask) {
    __shared__ int   idx_sh[TOK_PER_BLK];
    __shared__ float gate_sh[TOK_PER_BLK];

    int blk  = blockIdx.x;
    int tid  = threadIdx.x;          // 128 threads
    int base = blk * TOK_PER_BLK;
    int tokens = s - base;
    if (tokens > TOK_PER_BLK) tokens = TOK_PER_BLK;

    if (tid < tokens) {
        idx_sh[tid]  = g_idx[base + tid];
        gate_sh[tid] = g_gate[base + tid];
    }
    __syncthreads();

    if (tid < E) {
        int cnt = g_base[blk * E + tid];   // tokens routed to my expert before this chunk
        for (int t = 0; t < tokens; t++) {
            if (idx_sh[t] == tid) {        // smem broadcast read per iteration
                int r = cnt++;
                if (r < cap) {
                    size_t off = (((size_t)(base + t)) * E + (size_t)tid) * (size_t)cap + (size_t)r;
                    out[off] = gate_sh[t];
                    if (write_mask) out[mask_off + off] = 1.0f;
                }
            }
        }
    }
}

// ---------------------------------------------------------------------------
extern "C" void kernel_launch(void* const* d_in, const int* in_sizes, int n_in,
                              void* d_out, int out_size) {
    const float* in = (const float*)d_in[0];
    float* out = (float*)d_out;

    int total = in_sizes[0];
    int s = total / E;                 // e = 64 (static in reference)
    // capacity = floor(1.25 * s / e), made even, min 4
    int cap = (int)floor(1.25 * (double)s / (double)E);
    cap += (cap & 1);
    if (cap < 4) cap = 4;

    size_t sec = (size_t)s * E * (size_t)cap;          // elements per output tensor
    int write_mask = ((size_t)out_size >= 2 * sec) ? 1 : 0;

    int nchunks = (s + TOK_PER_BLK - 1) / TOK_PER_BLK;

    // 0) zero-fill entire output buffer
    size_t n_total = (size_t)out_size;
    size_t n4 = n_total / 4;
    zero_fill<<<4096, 256>>>((float4*)d_out, n4, out, n_total);

    // 1) router: argmax + gate + per-chunk histogram
    route_kernel<<<nchunks, TOK_PER_BLK>>>(in, s);

    // 2) cross-chunk exclusive prefix per expert
    prefix_kernel<<<1, E>>>(nchunks);

    // 3) in-order scan + scatter
    scatter_kernel<<<nchunks, TOK_PER_BLK>>>(out, s, cap, sec, write_mask);
}

// round 2
// speedup vs baseline: 1.0844x; 1.0844x over previous
#include <cuda_runtime.h>
#include <math.h>

#define E 64
#define TOK_PER_BLK 128
#define MAX_TOK 16384
#define MAX_CHUNKS (MAX_TOK / TOK_PER_BLK)

// Scratch (no allocations allowed)
__device__ int   g_idx[MAX_TOK];      // per-token argmax expert
__device__ float g_gate[MAX_TOK];     // per-token softmax prob at argmax
__device__ int   g_slot[MAX_TOK];     // per-token flat slot e*cap+r, or -1 if dropped
__device__ int   g_hist[MAX_CHUNKS * E];
__device__ int   g_base[MAX_CHUNKS * E];

// ---------------------------------------------------------------------------
// Kernel 1: per-token argmax + softmax prob at argmax + per-chunk histogram
// p(top1) = 1 / sum_i exp(x_i - x_max)
// ---------------------------------------------------------------------------
__global__ void route_kernel(const float* __restrict__ in, int s) {
    __shared__ float tile[TOK_PER_BLK][E + 1];  // +1 pad: conflict-free row reads
    __shared__ int hist[E];

    int blk  = blockIdx.x;
    int tid  = threadIdx.x;          // 128 threads
    int base = blk * TOK_PER_BLK;
    int tokens = s - base;
    if (tokens > TOK_PER_BLK) tokens = TOK_PER_BLK;

    // coalesced float4 load of [tokens x 64] into shared
    const float4* in4 = (const float4*)(in + (size_t)base * E);
    int n4 = tokens * E / 4;
    for (int i = tid; i < n4; i += blockDim.x) {
        float4 v = in4[i];
        int fl = i * 4;
        int t = fl >> 6;        // / 64
        int k = fl & 63;
        tile[t][k]     = v.x;
        tile[t][k + 1] = v.y;
        tile[t][k + 2] = v.z;
        tile[t][k + 3] = v.w;
    }
    if (tid < E) hist[tid] = 0;
    __syncthreads();

    if (tid < tokens) {
        // first-index argmax (matches jnp.argmax tie-breaking)
        float m = tile[tid][0];
        int am = 0;
#pragma unroll
        for (int k = 1; k < E; k++) {
            float v = tile[tid][k];
            if (v > m) { m = v; am = k; }
        }
        float sum = 0.f;
#pragma unroll
        for (int k = 0; k < E; k++)
            sum += __expf(tile[tid][k] - m);

        g_idx[base + tid]  = am;
        g_gate[base + tid] = 1.0f / sum;
        atomicAdd(&hist[am], 1);
    }
    __syncthreads();
    if (tid < E) g_hist[blk * E + tid] = hist[tid];
}

// ---------------------------------------------------------------------------
// Kernel 2: exclusive prefix over chunks, per expert
// ---------------------------------------------------------------------------
__global__ void prefix_kernel(int nchunks) {
    int e = threadIdx.x;  // 64 threads
    int run = 0;
    for (int b = 0; b < nchunks; b++) {
        g_base[b * E + e] = run;
        run += g_hist[b * E + e];
    }
}

// ---------------------------------------------------------------------------
// Kernel 3: parallel per-token rank -> flat slot (e*cap + r), -1 if dropped.
// rank = chunk_base[expert] + count of earlier tokens in chunk w/ same expert.
// ---------------------------------------------------------------------------
__global__ void slot_kernel(int s, int cap) {
    __shared__ int idx_sh[TOK_PER_BLK];

    int blk  = blockIdx.x;
    int tid  = threadIdx.x;          // 128 threads
    int base = blk * TOK_PER_BLK;
    int tokens = s - base;
    if (tokens > TOK_PER_BLK) tokens = TOK_PER_BLK;

    if (tid < tokens) idx_sh[tid] = g_idx[base + tid];
    __syncthreads();

    if (tid < tokens) {
        int e = idx_sh[tid];
        int r = g_base[blk * E + e];
        for (int t = 0; t < tid; t++)
            r += (idx_sh[t] == e);
        g_slot[base + tid] = (r < cap) ? (e * cap + r) : -1;
    }
}

// ---------------------------------------------------------------------------
// Kernel 4: fused fill + sparse write. One block per token. Each token owns
// a contiguous row of E*cap floats in each output tensor with <=1 nonzero.
// Branch-free SELs keep the store stream at full rate.
// ---------------------------------------------------------------------------
__global__ void fill_kernel(float* __restrict__ out, size_t sec, int cap,
                            int write_mask) {
    int t = blockIdx.x;
    int row = E * cap;               // elements per token per tensor (mult of 4)
    int n4 = row >> 2;

    int p = g_slot[t];
    float gv = g_gate[t];

    float4* __restrict__ c4 = (float4*)(out + (size_t)t * row);
    float4* __restrict__ m4 = (float4*)(out + sec + (size_t)t * row);

    for (int i = threadIdx.x; i < n4; i += blockDim.x) {
        int b = i << 2;
        float4 v, m;
        v.x = (p == b)     ? gv : 0.f;  m.x = (p == b)     ? 1.f : 0.f;
        v.y = (p == b + 1) ? gv : 0.f;  m.y = (p == b + 1) ? 1.f : 0.f;
        v.z = (p == b + 2) ? gv : 0.f;  m.z = (p == b + 2) ? 1.f : 0.f;
        v.w = (p == b + 3) ? gv : 0.f;  m.w = (p == b + 3) ? 1.f : 0.f;
        c4[i] = v;
        if (write_mask) m4[i] = m;
    }
}

// ---------------------------------------------------------------------------
// Kernel 5: zero any tail beyond the two tensors (output is poisoned 0xAA)
// ---------------------------------------------------------------------------
__global__ void tail_zero(float* __restrict__ out, size_t start, size_t end) {
    size_t i = start + blockIdx.x * (size_t)blockDim.x + threadIdx.x;
    size_t stride = gridDim.x * (size_t)blockDim.x;
    for (; i < end; i += stride) out[i] = 0.f;
}

// ---------------------------------------------------------------------------
extern "C" void kernel_launch(void* const* d_in, const int* in_sizes, int n_in,
                              void* d_out, int out_size) {
    const float* in = (const float*)d_in[0];
    float* out = (float*)d_out;

    int total = in_sizes[0];
    int s = total / E;
    // capacity = floor(1.25 * s / e), made even, min 4
    int cap = (int)floor(1.25 * (double)s / (double)E);
    cap += (cap & 1);
    if (cap < 4) cap = 4;

    size_t sec = (size_t)s * E * (size_t)cap;
    int write_mask = ((size_t)out_size >= 2 * sec) ? 1 : 0;

    int nchunks = (s + TOK_PER_BLK - 1) / TOK_PER_BLK;

    // 1) router: argmax + gate + per-chunk histogram
    route_kernel<<<nchunks, TOK_PER_BLK>>>(in, s);

    // 2) cross-chunk exclusive prefix per expert
    prefix_kernel<<<1, E>>>(nchunks);

    // 3) per-token flat slot
    slot_kernel<<<nchunks, TOK_PER_BLK>>>(s, cap);

    // 4) fused fill + sparse write (one block per token)
    fill_kernel<<<s, 256>>>(out, sec, cap, write_mask);

    // 5) tail beyond 2*sec, if any
    size_t covered = write_mask ? 2 * sec : sec;
    if ((size_t)out_size > covered) {
        tail_zero<<<256, 256>>>(out, covered, (size_t)out_size);
    }
}

// round 3
// speedup vs baseline: 1.2821x; 1.1823x over previous
#include <cuda_runtime.h>
#include <math.h>

#define E 64
#define TOK_PER_BLK 128
#define MAX_TOK 16384
#define MAX_CHUNKS (MAX_TOK / TOK_PER_BLK)

// Scratch (no allocations allowed)
__device__ int   g_idx[MAX_TOK];      // per-token argmax expert
__device__ float g_gate[MAX_TOK];     // per-token softmax prob at argmax
__device__ int   g_slot[MAX_TOK];     // per-token flat slot e*cap+r, or -1 if dropped
__device__ int   g_hist[MAX_CHUNKS * E];

// ---------------------------------------------------------------------------
// Kernel 1: per-token argmax + softmax prob at argmax + per-chunk histogram.
// 4 threads per token (16 experts each), combined via shfl within lane-groups
// of 4. 512 threads/block -> 128 tokens/block.
// ---------------------------------------------------------------------------
__global__ void route_kernel(const float* __restrict__ in, int s) {
    __shared__ int hist[E];

    int blk     = blockIdx.x;
    int tid     = threadIdx.x;        // 0..511
    int t_local = tid >> 2;           // token within chunk 0..127
    int part    = tid & 3;            // 16-expert slice 0..3
    int token   = blk * TOK_PER_BLK + t_local;
    bool valid  = (token < s);
    int  tok_c  = valid ? token : (s - 1);   // clamp so all lanes participate

    if (tid < E) hist[tid] = 0;

    // load 16 contiguous floats (4x float4); coalesced across the warp
    const float4* p4 = (const float4*)(in + (size_t)tok_c * E + part * 16);
    float4 a = p4[0], b = p4[1], c = p4[2], d = p4[3];
    float v[16] = {a.x, a.y, a.z, a.w, b.x, b.y, b.z, b.w,
                   c.x, c.y, c.z, c.w, d.x, d.y, d.z, d.w};

    // local first-index argmax over this thread's 16
    float m = v[0];
    int   am = part * 16;
#pragma unroll
    for (int k = 1; k < 16; k++) {
        if (v[k] > m) { m = v[k]; am = part * 16 + k; }
    }
    // combine across the 4 lanes of the token group (xor 1, 2 stays in group)
#pragma unroll
    for (int off = 1; off < 4; off <<= 1) {
        float mo = __shfl_xor_sync(0xffffffffu, m, off);
        int   ao = __shfl_xor_sync(0xffffffffu, am, off);
        if (mo > m || (mo == m && ao < am)) { m = mo; am = ao; }
    }
    // sum of exp(x - m) over all 64
    float sum = 0.f;
#pragma unroll
    for (int k = 0; k < 16; k++) sum += __expf(v[k] - m);
#pragma unroll
    for (int off = 1; off < 4; off <<= 1)
        sum += __shfl_xor_sync(0xffffffffu, sum, off);

    __syncthreads();                  // hist zeroed
    if (valid && part == 0) {
        g_idx[token]  = am;
        g_gate[token] = 1.0f / sum;
        atomicAdd(&hist[am], 1);
    }
    __syncthreads();
    if (tid < E) g_hist[blk * E + tid] = hist[tid];
}

// ---------------------------------------------------------------------------
// Kernel 2: fused cross-chunk prefix + per-token slot.
// Each block redundantly loads the full hist table (coalesced burst into
// smem), computes its own chunk's exclusive base, then O(1)-per-token
// in-chunk rank via __match_any_sync + per-warp count table.
// ---------------------------------------------------------------------------
__global__ void prefix_slot_kernel(int s, int cap, int nchunks) {
    __shared__ int hist_sh[MAX_CHUNKS * E];   // 32 KB
    __shared__ int base_sh[E];
    __shared__ int idx_sh[TOK_PER_BLK];
    __shared__ int warp_cnt[4][E + 1];

    int blk = blockIdx.x;
    int tid = threadIdx.x;            // 128
    int total = nchunks * E;
    for (int i = tid; i < total; i += TOK_PER_BLK) hist_sh[i] = g_hist[i];
    for (int i = tid; i < 4 * (E + 1); i += TOK_PER_BLK)
        ((int*)warp_cnt)[i] = 0;

    int base = blk * TOK_PER_BLK;
    int tokens = s - base;
    if (tokens > TOK_PER_BLK) tokens = TOK_PER_BLK;
    if (tid < tokens) idx_sh[tid] = g_idx[base + tid];
    __syncthreads();

    if (tid < E) {
        int r = 0;
        for (int c = 0; c < blk; c++) r += hist_sh[c * E + tid];
        base_sh[tid] = r;
    }

    int e = (tid < tokens) ? idx_sh[tid] : E;     // E = dummy bucket
    unsigned mask = __match_any_sync(0xffffffffu, e);
    int lane   = tid & 31;
    int w      = tid >> 5;
    int within = __popc(mask & ((1u << lane) - 1));
    if (within == 0) warp_cnt[w][e] = __popc(mask);
    __syncthreads();

    if (tid < tokens) {
        int r = base_sh[e] + within;
#pragma unroll
        for (int w2 = 0; w2 < 4; w2++)
            if (w2 < w) r += warp_cnt[w2][e];
        g_slot[base + tid] = (r < cap) ? (e * cap + r) : -1;
    }
}

// ---------------------------------------------------------------------------
// Kernel 3: fill. One block per token; unconditional streaming zero stores
// (pure STG.128 stream), then a single scalar fix-up for the <=1 nonzero.
// ---------------------------------------------------------------------------
__global__ void fill_kernel(float* __restrict__ out, size_t sec, int cap,
                            int write_mask) {
    int t   = blockIdx.x;
    int row = E * cap;                // multiple of 4
    int n4  = row >> 2;

    float4* __restrict__ c4 = (float4*)(out + (size_t)t * row);
    float4* __restrict__ m4 = (float4*)(out + sec + (size_t)t * row);
    float4 z = make_float4(0.f, 0.f, 0.f, 0.f);

    if (write_mask) {
        for (int i = threadIdx.x; i < n4; i += blockDim.x) {
            __stcs(&c4[i], z);
            __stcs(&m4[i], z);
        }
    } else {
        for (int i = threadIdx.x; i < n4; i += blockDim.x)
            __stcs(&c4[i], z);
    }
    __syncthreads();

    if (threadIdx.x == 0) {
        int p = g_slot[t];
        if (p >= 0) {
            out[(size_t)t * row + p] = g_gate[t];
            if (write_mask) out[sec + (size_t)t * row + p] = 1.0f;
        }
    }
}

// ---------------------------------------------------------------------------
// Kernel 4: zero any tail beyond the two tensors (output poisoned 0xAA)
// ---------------------------------------------------------------------------
__global__ void tail_zero(float* __restrict__ out, size_t start, size_t end) {
    size_t i = start + blockIdx.x * (size_t)blockDim.x + threadIdx.x;
    size_t stride = gridDim.x * (size_t)blockDim.x;
    for (; i < end; i += stride) out[i] = 0.f;
}

// ---------------------------------------------------------------------------
extern "C" void kernel_launch(void* const* d_in, const int* in_sizes, int n_in,
                              void* d_out, int out_size) {
    const float* in = (const float*)d_in[0];
    float* out = (float*)d_out;

    int total = in_sizes[0];
    int s = total / E;
    int cap = (int)floor(1.25 * (double)s / (double)E);
    cap += (cap & 1);
    if (cap < 4) cap = 4;

    size_t sec = (size_t)s * E * (size_t)cap;
    int write_mask = ((size_t)out_size >= 2 * sec) ? 1 : 0;

    int nchunks = (s + TOK_PER_BLK - 1) / TOK_PER_BLK;

    // 1) router: argmax + gate + per-chunk histogram (4 threads/token)
    route_kernel<<<nchunks, 512>>>(in, s);

    // 2) fused prefix + slot
    prefix_slot_kernel<<<nchunks, TOK_PER_BLK>>>(s, cap, nchunks);

    // 3) streaming fill + scalar fix-up
    fill_kernel<<<s, 256>>>(out, sec, cap, write_mask);

    // 4) tail beyond 2*sec, if any
    size_t covered = write_mask ? 2 * sec : sec;
    if ((size_t)out_size > covered) {
        tail_zero<<<256, 256>>>(out, covered, (size_t)out_size);
    }
}